// round 1
// baseline (speedup 1.0000x reference)
#include <cuda_runtime.h>
#include <cuda_bf16.h>
#include <math.h>

#define BB 16
#define NN 25200
#define NCLS 80
#define KPRE 1024
#define MAXDET 300
#define OUTC 89
#define CAPB 3072

// ---------------- scratch (device globals; no allocation) ----------------
__device__ unsigned           g_scorebits[BB*NN];
__device__ int                g_cls[BB*NN];
__device__ unsigned           g_hist[BB*512];
__device__ int                g_thr[BB];
__device__ unsigned           g_cntA[BB];
__device__ unsigned           g_cntB[BB];
__device__ unsigned long long g_listA[BB*1024];
__device__ unsigned long long g_listB[BB*CAPB];
__device__ unsigned long long g_top[BB*KPRE];
__device__ float4             g_boxes[BB*KPRE];
__device__ unsigned           g_validw[BB*32];
__device__ int                g_nvalid[BB];
__device__ unsigned           g_mask[BB*KPRE*32];
__device__ int                g_sel[BB*MAXDET];
__device__ int                g_nk[BB];

// ---------------- zero the per-launch counters/hist ----------------
__global__ void k_zero() {
    int t = blockIdx.x * blockDim.x + threadIdx.x;
    if (t < BB*512) g_hist[t] = 0;
    if (t < BB) { g_cntA[t] = 0; g_cntB[t] = 0; }
}

// ---------------- phase 1: per-anchor score/argmax + histogram ----------------
__global__ void k_score(const float* __restrict__ pred) {
    int warp = (blockIdx.x * blockDim.x + threadIdx.x) >> 5;
    int lane = threadIdx.x & 31;
    if (warp >= BB*NN) return;
    size_t base = (size_t)warp * 85;
    float l0 = pred[base + lane];
    float l1 = pred[base + 32 + lane];
    float l2 = (lane < 21) ? pred[base + 64 + lane] : 0.f;
    float obj = __shfl_sync(0xffffffffu, l0, 4);

    float bv = -1.f; int bi = 0x7fffffff;
    if (lane >= 5) { float p = l0 * obj; int c = lane - 5;  if (p > bv) { bv = p; bi = c; } }
    { float p = l1 * obj; int c = 27 + lane; if (p > bv || (p == bv && c < bi)) { bv = p; bi = c; } }
    if (lane < 21) { float p = l2 * obj; int c = 59 + lane; if (p > bv || (p == bv && c < bi)) { bv = p; bi = c; } }

    #pragma unroll
    for (int off = 16; off; off >>= 1) {
        float ov = __shfl_xor_sync(0xffffffffu, bv, off);
        int   oi = __shfl_xor_sync(0xffffffffu, bi, off);
        if (ov > bv || (ov == bv && oi < bi)) { bv = ov; bi = oi; }
    }
    if (lane == 0) {
        float conf = bv;
        float score = (obj > 0.4f && conf > 0.4f) ? conf : 0.f;
        unsigned bits = __float_as_uint(score);
        g_scorebits[warp] = bits;
        g_cls[warp] = bi;
        if (bits) {
            int b = warp / NN;
            int bin = (int)(bits >> 16) - 0x3E00;
            bin = bin < 0 ? 0 : (bin > 511 ? 511 : bin);
            atomicAdd(&g_hist[b*512 + bin], 1u);
        }
    }
}

// ---------------- phase 2b: per-batch threshold bin via suffix sum ----------------
__global__ void k_thresh() {
    __shared__ unsigned s[512];
    int b = blockIdx.x, t = threadIdx.x;
    s[t] = g_hist[b*512 + t];
    __syncthreads();
    for (int off = 1; off < 512; off <<= 1) {
        unsigned v = (t + off < 512) ? s[t + off] : 0u;
        __syncthreads();
        s[t] += v;
        __syncthreads();
    }
    unsigned suf  = s[t];
    unsigned sufn = (t < 511) ? s[t + 1] : 0u;
    if (t == 0 && suf < KPRE) g_thr[b] = -1;
    if (suf >= KPRE && sufn < KPRE) g_thr[b] = t;
}

// ---------------- phase 2c: compact candidates ----------------
__global__ void k_compact() {
    int a = blockIdx.x * blockDim.x + threadIdx.x;
    if (a >= BB*NN) return;
    unsigned bits = g_scorebits[a];
    if (!bits) return;
    int b = a / NN;
    unsigned ai = (unsigned)(a - b*NN);
    int bin = (int)(bits >> 16) - 0x3E00;
    bin = bin < 0 ? 0 : (bin > 511 ? 511 : bin);
    int T = g_thr[b];
    unsigned long long key = ((unsigned long long)bits << 32) | (0xFFFFFFFFu - ai);
    if (bin > T) {
        unsigned p = atomicAdd(&g_cntA[b], 1u);
        if (p < 1024u) g_listA[b*1024 + p] = key;
    } else if (bin == T) {
        unsigned p = atomicAdd(&g_cntB[b], 1u);
        if (p < (unsigned)CAPB) g_listB[b*CAPB + p] = key;
    }
}

// ---------------- phase 2d: bitonic sort candidates; emit top-1024, boxes, valid bits ----------------
__global__ void k_sort(const float* __restrict__ pred) {
    __shared__ unsigned long long sk[4096];
    __shared__ unsigned svw[32];
    int b = blockIdx.x, tid = threadIdx.x; // 1024 threads
    unsigned nA = min(g_cntA[b], 1024u);
    unsigned nB = min(g_cntB[b], (unsigned)CAPB);
    unsigned tot = nA + nB;
    unsigned S = 1024; while (S < tot) S <<= 1;   // <= 4096
    for (unsigned i = tid; i < S; i += 1024) {
        unsigned long long v = 0ull;
        if (i < nA) v = g_listA[b*1024 + i];
        else if (i < tot) v = g_listB[b*CAPB + (i - nA)];
        sk[i] = v;
    }
    __syncthreads();
    for (unsigned k = 2; k <= S; k <<= 1) {
        for (unsigned j = k >> 1; j > 0; j >>= 1) {
            for (unsigned i = tid; i < S; i += 1024) {
                unsigned ixj = i ^ j;
                if (ixj > i) {
                    bool up = ((i & k) == 0);
                    unsigned long long x = sk[i], y = sk[ixj];
                    bool sw = up ? (x < y) : (x > y);   // descending
                    if (sw) { sk[i] = y; sk[ixj] = x; }
                }
            }
            __syncthreads();
        }
    }
    // emit
    {
        unsigned long long key = sk[tid];
        unsigned bits = (unsigned)(key >> 32);
        unsigned anchor = bits ? (0xFFFFFFFFu - (unsigned)key) : 0u;
        g_top[b*KPRE + tid] = ((unsigned long long)bits << 32) | anchor;
        float4 bx = make_float4(0.f, 0.f, 0.f, 0.f);
        if (bits) {
            size_t base = ((size_t)b*NN + anchor) * 85;
            float x = pred[base], y = pred[base+1], w = pred[base+2], h = pred[base+3];
            float off = (float)g_cls[b*NN + anchor] * 4096.0f;
            bx.x = (x - w*0.5f) + off;
            bx.y = (y - h*0.5f) + off;
            bx.z = (x + w*0.5f) + off;
            bx.w = (y + h*0.5f) + off;
        }
        g_boxes[b*KPRE + tid] = bx;
        unsigned bal = __ballot_sync(0xffffffffu, bits != 0u);
        if ((tid & 31) == 0) { svw[tid >> 5] = bal; g_validw[b*32 + (tid >> 5)] = bal; }
    }
    __syncthreads();
    if (tid == 0) {
        int nv = 0;
        for (int w = 0; w < 32; w++) nv += __popc(svw[w]);
        g_nvalid[b] = nv;
    }
}

// ---------------- phase 3: IoU suppression bit-mask (j > i baked in) ----------------
__global__ void k_iou() {
    __shared__ float4 sb[1024];
    __shared__ float  sa[1024];
    __shared__ unsigned tileS[32][33];
    int b = blockIdx.y, tile = blockIdx.x;
    int tid = threadIdx.x;
    float4 v = g_boxes[b*KPRE + tid];
    sb[tid] = v;
    sa[tid] = (v.z - v.x) * (v.w - v.y);
    __syncthreads();

    int w = tid >> 5, rl = tid & 31;
    int r = tile*32 + rl;
    float4 rb_ = sb[r];
    float  ra  = sa[r];
    unsigned bits = 0u;
    int j0 = w * 32;
    #pragma unroll 4
    for (int t = 0; t < 32; t++) {
        int j = j0 + t;
        float4 cb = sb[j];
        float ltx = fmaxf(rb_.x, cb.x), lty = fmaxf(rb_.y, cb.y);
        float rbx = fminf(rb_.z, cb.z), rby = fminf(rb_.w, cb.w);
        float iw = fmaxf(rbx - ltx, 0.f), ih = fmaxf(rby - lty, 0.f);
        float inter = iw * ih;
        float den = ((ra + sa[j]) - inter) + 1e-7f;
        bool sup = (j > r) && (__fdiv_rn(inter, den) > 0.45f);
        bits |= sup ? (1u << t) : 0u;
    }
    tileS[rl][w] = bits;
    __syncthreads();
    int rl2 = tid >> 5, w2 = tid & 31;
    g_mask[((size_t)b*KPRE + tile*32 + rl2) * 32 + w2] = tileS[rl2][w2];
}

// ---------------- phase 4: serial greedy reduction, one warp per batch ----------------
__global__ void k_nms() {
    int b = blockIdx.x, lane = threadIdx.x;
    const unsigned* mp = &g_mask[(size_t)b*KPRE*32];
    unsigned alive = g_validw[b*32 + lane];
    unsigned cur = mp[lane];
    int cnt = 0;
    for (int i = 0; i < KPRE; i++) {
        unsigned nxt = (i < KPRE-1) ? mp[(size_t)(i+1)*32 + lane] : 0u;
        unsigned aw = __shfl_sync(0xffffffffu, alive, i >> 5);
        if (aw & (1u << (i & 31))) {
            alive &= ~cur;
            if (lane == 0 && cnt < MAXDET) g_sel[b*MAXDET + cnt] = i;
            cnt++;
        }
        cur = nxt;
    }
    if (lane == 0) g_nk[b] = cnt < MAXDET ? cnt : MAXDET;
}

// ---------------- phase 5: gather + emit output rows ----------------
__global__ void k_out(const float* __restrict__ pred,
                      const float* __restrict__ conf_logits,
                      const float* __restrict__ logits,
                      const float* __restrict__ head,
                      float* __restrict__ out) {
    int gw = (blockIdx.x * blockDim.x + threadIdx.x) >> 5;
    int lane = threadIdx.x & 31;
    if (gw >= BB*MAXDET) return;
    int b = gw / MAXDET, r = gw - b*MAXDET;
    size_t obase = (size_t)gw * OUTC;
    int nk = g_nk[b];
    if (r < nk) {
        int slot = g_sel[b*MAXDET + r];
        unsigned long long key = g_top[b*KPRE + slot];
        float score = __uint_as_float((unsigned)(key >> 32));
        unsigned anchor = (unsigned)key;
        size_t a = (size_t)b*NN + anchor;
        float objsig = 1.f / (1.f + expf(-conf_logits[a*5 + 4]));
        for (int c = lane; c < OUTC; c += 32) {
            float val;
            if (c < 4) {
                float x = pred[a*85], y = pred[a*85+1], w = pred[a*85+2], h = pred[a*85+3];
                val = (c == 0) ? x - w*0.5f : (c == 1) ? y - h*0.5f
                    : (c == 2) ? x + w*0.5f : y + h*0.5f;
            } else if (c == 4)  val = score;
            else if (c == 5)    val = (float)g_cls[a];
            else if (c < 86)    val = (1.f / (1.f + expf(-logits[a*80 + (c - 6)]))) * objsig;
            else if (c == 86)   val = objsig;
            else if (c == 87)   val = head[a];
            else                val = 1.f;
            out[obase + c] = val;
        }
    } else {
        for (int c = lane; c < OUTC; c += 32) out[obase + c] = 0.f;
    }
}

extern "C" void kernel_launch(void* const* d_in, const int* in_sizes, int n_in,
                              void* d_out, int out_size) {
    const float* pred = (const float*)d_in[0];
    const float* cl   = (const float*)d_in[1];
    const float* lg   = (const float*)d_in[2];
    const float* hd   = (const float*)d_in[3];
    float* out = (float*)d_out;

    k_zero<<<32, 256>>>();
    {
        long threads = (long)BB * NN * 32;
        int blocks = (int)((threads + 255) / 256);
        k_score<<<blocks, 256>>>(pred);
    }
    k_thresh<<<BB, 512>>>();
    k_compact<<<(BB*NN + 255) / 256, 256>>>();
    k_sort<<<BB, 1024>>>(pred);
    k_iou<<<dim3(32, BB), 1024>>>();
    k_nms<<<BB, 32>>>();
    k_out<<<(BB*MAXDET*32 + 255) / 256, 256>>>(pred, cl, lg, hd, out);
}

// round 2
// speedup vs baseline: 1.9234x; 1.9234x over previous
#include <cuda_runtime.h>
#include <cuda_bf16.h>
#include <math.h>

#define BB 16
#define NN 25200
#define NCLS 80
#define KPRE 1024
#define MAXDET 300
#define OUTC 89

// ---------------- scratch (device globals; zero-initialized at load) ----------------
__device__ int                g_cls[BB*NN];
__device__ unsigned           g_cnt[BB];                 // zeroed at end of k_sortsel
__device__ unsigned long long g_cand[BB*NN];
__device__ unsigned long long g_top[BB*KPRE];
__device__ float4             g_boxes[BB*KPRE];
__device__ unsigned           g_validw[BB*32];
__device__ unsigned           g_mask[BB*KPRE*32];
__device__ int                g_sel[BB*MAXDET];
__device__ int                g_nk[BB];

static __device__ __forceinline__ int score_bin(unsigned bits) {
    int bin = (int)(bits >> 16) - 0x3E00;
    return bin < 0 ? 0 : (bin > 511 ? 511 : bin);
}

// ---------------- phase 1: per-anchor score/argmax + compacted candidate push ----------------
__global__ void k_score(const float* __restrict__ pred) {
    __shared__ unsigned long long sbuf[8];
    __shared__ unsigned scnt;
    __shared__ unsigned sbase;
    if (threadIdx.x == 0) scnt = 0;
    __syncthreads();

    int warp = (blockIdx.x * blockDim.x + threadIdx.x) >> 5;   // global anchor id
    int lane = threadIdx.x & 31;
    size_t base = (size_t)warp * 85;
    float l0 = pred[base + lane];
    float l1 = pred[base + 32 + lane];
    float l2 = (lane < 21) ? pred[base + 64 + lane] : 0.f;
    float obj = __shfl_sync(0xffffffffu, l0, 4);

    float bv = -1.f; int bi = 0x7fffffff;
    if (lane >= 5) { float p = l0 * obj; int c = lane - 5;  if (p > bv) { bv = p; bi = c; } }
    { float p = l1 * obj; int c = 27 + lane; if (p > bv || (p == bv && c < bi)) { bv = p; bi = c; } }
    if (lane < 21) { float p = l2 * obj; int c = 59 + lane; if (p > bv || (p == bv && c < bi)) { bv = p; bi = c; } }

    #pragma unroll
    for (int off = 16; off; off >>= 1) {
        float ov = __shfl_xor_sync(0xffffffffu, bv, off);
        int   oi = __shfl_xor_sync(0xffffffffu, bi, off);
        if (ov > bv || (ov == bv && oi < bi)) { bv = ov; bi = oi; }
    }
    int b = warp / NN;
    if (lane == 0) {
        float conf = bv;
        float score = (obj > 0.4f && conf > 0.4f) ? conf : 0.f;
        unsigned bits = __float_as_uint(score);
        g_cls[warp] = bi;
        if (bits) {
            unsigned ai = (unsigned)(warp - b*NN);
            unsigned long long key =
                ((unsigned long long)bits << 32) | (0xFFFFFFFFu - ai);
            unsigned p = atomicAdd(&scnt, 1u);
            sbuf[p] = key;
        }
    }
    __syncthreads();
    if (threadIdx.x == 0 && scnt) sbase = atomicAdd(&g_cnt[b], scnt);
    __syncthreads();
    if (threadIdx.x < scnt)
        g_cand[(size_t)b*NN + sbase + threadIdx.x] = sbuf[threadIdx.x];
}

// ---------------- phase 2: per-batch hist + threshold + filter + bitonic top-1024 ----------------
__global__ void k_sortsel(const float* __restrict__ pred) {
    __shared__ unsigned long long sk[4096];
    __shared__ unsigned hist[512];
    __shared__ int sT;
    __shared__ unsigned nA, nB;
    __shared__ unsigned svw[32];
    int b = blockIdx.x, tid = threadIdx.x;   // 1024 threads

    for (int i = tid; i < 4096; i += 1024) sk[i] = 0ull;
    if (tid < 512) hist[tid] = 0u;
    if (tid == 0) { nA = 0; nB = 0; }
    __syncthreads();

    unsigned nc = min(g_cnt[b], (unsigned)NN);
    const unsigned long long* cand = &g_cand[(size_t)b*NN];
    for (unsigned i = tid; i < nc; i += 1024) {
        unsigned bits = (unsigned)(cand[i] >> 32);
        atomicAdd(&hist[score_bin(bits)], 1u);
    }
    __syncthreads();
    // suffix sum over 512 bins
    for (int off = 1; off < 512; off <<= 1) {
        unsigned v = 0;
        if (tid < 512 && tid + off < 512) v = hist[tid + off];
        __syncthreads();
        if (tid < 512) hist[tid] += v;
        __syncthreads();
    }
    if (tid < 512) {
        unsigned suf  = hist[tid];
        unsigned sufn = (tid < 511) ? hist[tid + 1] : 0u;
        if (tid == 0 && suf < (unsigned)KPRE) sT = -1;
        if (suf >= (unsigned)KPRE && sufn < (unsigned)KPRE) sT = tid;
    }
    __syncthreads();
    int T = sT;
    // scatter: bin>T -> [0,1024), bin==T -> [1024, 4096)
    for (unsigned i = tid; i < nc; i += 1024) {
        unsigned long long key = cand[i];
        int bin = score_bin((unsigned)(key >> 32));
        if (bin > T) {
            unsigned p = atomicAdd(&nA, 1u);
            if (p < 1024u) sk[p] = key;
        } else if (bin == T) {
            unsigned p = atomicAdd(&nB, 1u);
            if (p < 3072u) sk[1024u + p] = key;
        }
    }
    __syncthreads();
    unsigned used = 1024u + min(nB, 3072u);
    unsigned S = (used <= 2048u) ? 2048u : 4096u;
    // bitonic sort descending
    for (unsigned k2 = 2; k2 <= S; k2 <<= 1) {
        for (unsigned j = k2 >> 1; j > 0; j >>= 1) {
            for (unsigned i = tid; i < S; i += 1024) {
                unsigned ixj = i ^ j;
                if (ixj > i) {
                    bool up = ((i & k2) == 0);
                    unsigned long long x = sk[i], y = sk[ixj];
                    bool sw = up ? (x < y) : (x > y);
                    if (sw) { sk[i] = y; sk[ixj] = x; }
                }
            }
            __syncthreads();
        }
    }
    // emit top-1024
    {
        unsigned long long key = sk[tid];
        unsigned bits = (unsigned)(key >> 32);
        unsigned anchor = bits ? (0xFFFFFFFFu - (unsigned)key) : 0u;
        g_top[b*KPRE + tid] = ((unsigned long long)bits << 32) | anchor;
        float4 bx = make_float4(0.f, 0.f, 0.f, 0.f);
        if (bits) {
            size_t pb = ((size_t)b*NN + anchor) * 85;
            float x = pred[pb], y = pred[pb+1], w = pred[pb+2], h = pred[pb+3];
            float off = (float)g_cls[b*NN + anchor] * 4096.0f;
            bx.x = (x - w*0.5f) + off;
            bx.y = (y - h*0.5f) + off;
            bx.z = (x + w*0.5f) + off;
            bx.w = (y + h*0.5f) + off;
        }
        g_boxes[b*KPRE + tid] = bx;
        unsigned bal = __ballot_sync(0xffffffffu, bits != 0u);
        if ((tid & 31) == 0) g_validw[b*32 + (tid >> 5)] = bal;
    }
    __syncthreads();
    if (tid == 0) g_cnt[b] = 0;   // reset for next replay
}

// ---------------- phase 3: IoU suppression bit-mask (upper triangle only) ----------------
__global__ void k_iou() {
    __shared__ float4 sb[1024];
    __shared__ float  sa[1024];
    __shared__ unsigned tileS[32][33];
    int b = blockIdx.y, tile = blockIdx.x;
    int tid = threadIdx.x;
    float4 v = g_boxes[b*KPRE + tid];
    sb[tid] = v;
    sa[tid] = (v.z - v.x) * (v.w - v.y);
    __syncthreads();

    int w = tid >> 5, rl = tid & 31;
    int r = tile*32 + rl;
    unsigned bits = 0u;
    if (w >= tile) {   // words below the diagonal are all-zero (j>i only)
        float4 rb_ = sb[r];
        float  ra  = sa[r];
        int j0 = w * 32;
        #pragma unroll 4
        for (int t = 0; t < 32; t++) {
            int j = j0 + t;
            float4 cb = sb[j];
            float ltx = fmaxf(rb_.x, cb.x), lty = fmaxf(rb_.y, cb.y);
            float rbx = fminf(rb_.z, cb.z), rby = fminf(rb_.w, cb.w);
            float iw = fmaxf(rbx - ltx, 0.f), ih = fmaxf(rby - lty, 0.f);
            float inter = iw * ih;
            float den = ((ra + sa[j]) - inter) + 1e-7f;
            float thr = 0.45f * den;
            bool sup;
            if (inter > thr * (1.0f + 1e-5f))       sup = true;
            else if (inter < thr * (1.0f - 1e-5f))  sup = false;
            else                                    sup = (__fdiv_rn(inter, den) > 0.45f);
            sup = sup && (j > r);
            bits |= sup ? (1u << t) : 0u;
        }
    }
    tileS[rl][w] = bits;
    __syncthreads();
    int rl2 = tid >> 5, w2 = tid & 31;
    g_mask[((size_t)b*KPRE + tile*32 + rl2) * 32 + w2] = tileS[rl2][w2];
}

// ---------------- phase 4: serial greedy reduction, early exit at 300 kept ----------------
__global__ void k_nms() {
    int b = blockIdx.x, lane = threadIdx.x;
    const unsigned* mp = &g_mask[(size_t)b*KPRE*32];
    unsigned alive = g_validw[b*32 + lane];
    unsigned cur = mp[lane];
    int cnt = 0;
    for (int i = 0; i < KPRE; i++) {
        unsigned nxt = (i < KPRE-1) ? mp[(size_t)(i+1)*32 + lane] : 0u;
        unsigned aw = __shfl_sync(0xffffffffu, alive, i >> 5);
        if (aw & (1u << (i & 31))) {
            alive &= ~cur;
            if (lane == 0) g_sel[b*MAXDET + cnt] = i;
            cnt++;
            if (cnt == MAXDET) break;
        }
        cur = nxt;
    }
    if (lane == 0) g_nk[b] = cnt;
}

// ---------------- phase 5: gather + emit output rows ----------------
__global__ void k_out(const float* __restrict__ pred,
                      const float* __restrict__ conf_logits,
                      const float* __restrict__ logits,
                      const float* __restrict__ head,
                      float* __restrict__ out) {
    int gw = (blockIdx.x * blockDim.x + threadIdx.x) >> 5;
    int lane = threadIdx.x & 31;
    if (gw >= BB*MAXDET) return;
    int b = gw / MAXDET, r = gw - b*MAXDET;
    size_t obase = (size_t)gw * OUTC;
    int nk = g_nk[b];
    if (r < nk) {
        int slot = g_sel[b*MAXDET + r];
        unsigned long long key = g_top[b*KPRE + slot];
        float score = __uint_as_float((unsigned)(key >> 32));
        unsigned anchor = (unsigned)key;
        size_t a = (size_t)b*NN + anchor;
        float objsig = 1.f / (1.f + expf(-conf_logits[a*5 + 4]));
        for (int c = lane; c < OUTC; c += 32) {
            float val;
            if (c < 4) {
                float x = pred[a*85], y = pred[a*85+1], w = pred[a*85+2], h = pred[a*85+3];
                val = (c == 0) ? x - w*0.5f : (c == 1) ? y - h*0.5f
                    : (c == 2) ? x + w*0.5f : y + h*0.5f;
            } else if (c == 4)  val = score;
            else if (c == 5)    val = (float)g_cls[a];
            else if (c < 86)    val = (1.f / (1.f + expf(-logits[a*80 + (c - 6)]))) * objsig;
            else if (c == 86)   val = objsig;
            else if (c == 87)   val = head[a];
            else                val = 1.f;
            out[obase + c] = val;
        }
    } else {
        for (int c = lane; c < OUTC; c += 32) out[obase + c] = 0.f;
    }
}

extern "C" void kernel_launch(void* const* d_in, const int* in_sizes, int n_in,
                              void* d_out, int out_size) {
    const float* pred = (const float*)d_in[0];
    const float* cl   = (const float*)d_in[1];
    const float* lg   = (const float*)d_in[2];
    const float* hd   = (const float*)d_in[3];
    float* out = (float*)d_out;

    {
        // one warp per anchor, 8 anchors per 256-thread block; 25200 % 8 == 0
        int blocks = (BB*NN) / 8;
        k_score<<<blocks, 256>>>(pred);
    }
    k_sortsel<<<BB, 1024>>>(pred);
    k_iou<<<dim3(32, BB), 1024>>>();
    k_nms<<<BB, 32>>>();
    k_out<<<(BB*MAXDET*32 + 255) / 256, 256>>>(pred, cl, lg, hd, out);
}

// round 3
// speedup vs baseline: 2.1608x; 1.1234x over previous
#include <cuda_runtime.h>
#include <cuda_bf16.h>
#include <math.h>

#define BB 16
#define NN 25200
#define NCLS 80
#define KPRE 1024
#define MAXDET 300
#define OUTC 89

// ---------------- scratch (device globals; zero-initialized at load) ----------------
__device__ int                g_cls[BB*NN];
__device__ unsigned           g_cnt[BB];                 // zeroed at end of k_sortsel
__device__ unsigned long long g_cand[BB*NN];
__device__ unsigned long long g_top[BB*KPRE];
__device__ float4             g_boxes[BB*KPRE];
__device__ unsigned           g_validw[BB*32];
__device__ unsigned           g_mask[BB*KPRE*32];
__device__ int                g_sel[BB*MAXDET];
__device__ int                g_nk[BB];

static __device__ __forceinline__ int score_bin(unsigned bits) {
    int bin = (int)(bits >> 16) - 0x3E00;
    return bin < 0 ? 0 : (bin > 511 ? 511 : bin);
}

// ---------------- phase 1: per-anchor score/argmax + compacted candidate push ----------------
__global__ void k_score(const float* __restrict__ pred) {
    __shared__ unsigned long long sbuf[8];
    __shared__ unsigned scnt;
    __shared__ unsigned sbase;
    if (threadIdx.x == 0) scnt = 0;
    __syncthreads();

    int warp = (blockIdx.x * blockDim.x + threadIdx.x) >> 5;   // global anchor id
    int lane = threadIdx.x & 31;
    size_t base = (size_t)warp * 85;
    float l0 = pred[base + lane];
    float l1 = pred[base + 32 + lane];
    float l2 = (lane < 21) ? pred[base + 64 + lane] : 0.f;
    float obj = __shfl_sync(0xffffffffu, l0, 4);

    float bv = -1.f; int bi = 0x7fffffff;
    if (lane >= 5) { float p = l0 * obj; int c = lane - 5;  if (p > bv) { bv = p; bi = c; } }
    { float p = l1 * obj; int c = 27 + lane; if (p > bv || (p == bv && c < bi)) { bv = p; bi = c; } }
    if (lane < 21) { float p = l2 * obj; int c = 59 + lane; if (p > bv || (p == bv && c < bi)) { bv = p; bi = c; } }

    #pragma unroll
    for (int off = 16; off; off >>= 1) {
        float ov = __shfl_xor_sync(0xffffffffu, bv, off);
        int   oi = __shfl_xor_sync(0xffffffffu, bi, off);
        if (ov > bv || (ov == bv && oi < bi)) { bv = ov; bi = oi; }
    }
    int b = warp / NN;
    if (lane == 0) {
        float conf = bv;
        float score = (obj > 0.4f && conf > 0.4f) ? conf : 0.f;
        unsigned bits = __float_as_uint(score);
        g_cls[warp] = bi;
        if (bits) {
            unsigned ai = (unsigned)(warp - b*NN);
            unsigned long long key =
                ((unsigned long long)bits << 32) | (0xFFFFFFFFu - ai);
            unsigned p = atomicAdd(&scnt, 1u);
            sbuf[p] = key;
        }
    }
    __syncthreads();
    if (threadIdx.x == 0 && scnt) sbase = atomicAdd(&g_cnt[b], scnt);
    __syncthreads();
    if (threadIdx.x < scnt)
        g_cand[(size_t)b*NN + sbase + threadIdx.x] = sbuf[threadIdx.x];
}

// ---------------- phase 2: per-batch hist + threshold + filter + bitonic top-1024 ----------------
__global__ void k_sortsel(const float* __restrict__ pred) {
    __shared__ unsigned long long sk[4096];
    __shared__ unsigned hist[512];
    __shared__ int sT;
    __shared__ unsigned nA, nB;
    int b = blockIdx.x, tid = threadIdx.x;   // 1024 threads

    for (int i = tid; i < 4096; i += 1024) sk[i] = 0ull;
    if (tid < 512) hist[tid] = 0u;
    if (tid == 0) { nA = 0; nB = 0; }
    __syncthreads();

    unsigned nc = min(g_cnt[b], (unsigned)NN);
    const unsigned long long* cand = &g_cand[(size_t)b*NN];
    for (unsigned i = tid; i < nc; i += 1024) {
        unsigned bits = (unsigned)(cand[i] >> 32);
        atomicAdd(&hist[score_bin(bits)], 1u);
    }
    __syncthreads();
    // suffix sum over 512 bins
    for (int off = 1; off < 512; off <<= 1) {
        unsigned v = 0;
        if (tid < 512 && tid + off < 512) v = hist[tid + off];
        __syncthreads();
        if (tid < 512) hist[tid] += v;
        __syncthreads();
    }
    if (tid < 512) {
        unsigned suf  = hist[tid];
        unsigned sufn = (tid < 511) ? hist[tid + 1] : 0u;
        if (tid == 0 && suf < (unsigned)KPRE) sT = -1;
        if (suf >= (unsigned)KPRE && sufn < (unsigned)KPRE) sT = tid;
    }
    __syncthreads();
    int T = sT;
    // scatter: bin>T -> [0,1024), bin==T -> [1024, 4096)
    for (unsigned i = tid; i < nc; i += 1024) {
        unsigned long long key = cand[i];
        int bin = score_bin((unsigned)(key >> 32));
        if (bin > T) {
            unsigned p = atomicAdd(&nA, 1u);
            if (p < 1024u) sk[p] = key;
        } else if (bin == T) {
            unsigned p = atomicAdd(&nB, 1u);
            if (p < 3072u) sk[1024u + p] = key;
        }
    }
    __syncthreads();
    unsigned used = 1024u + min(nB, 3072u);
    unsigned S = (used <= 2048u) ? 2048u : 4096u;
    // bitonic sort descending
    for (unsigned k2 = 2; k2 <= S; k2 <<= 1) {
        for (unsigned j = k2 >> 1; j > 0; j >>= 1) {
            for (unsigned i = tid; i < S; i += 1024) {
                unsigned ixj = i ^ j;
                if (ixj > i) {
                    bool up = ((i & k2) == 0);
                    unsigned long long x = sk[i], y = sk[ixj];
                    bool sw = up ? (x < y) : (x > y);
                    if (sw) { sk[i] = y; sk[ixj] = x; }
                }
            }
            __syncthreads();
        }
    }
    // emit top-1024
    {
        unsigned long long key = sk[tid];
        unsigned bits = (unsigned)(key >> 32);
        unsigned anchor = bits ? (0xFFFFFFFFu - (unsigned)key) : 0u;
        g_top[b*KPRE + tid] = ((unsigned long long)bits << 32) | anchor;
        float4 bx = make_float4(0.f, 0.f, 0.f, 0.f);
        if (bits) {
            size_t pb = ((size_t)b*NN + anchor) * 85;
            float x = pred[pb], y = pred[pb+1], w = pred[pb+2], h = pred[pb+3];
            float off = (float)g_cls[b*NN + anchor] * 4096.0f;
            bx.x = (x - w*0.5f) + off;
            bx.y = (y - h*0.5f) + off;
            bx.z = (x + w*0.5f) + off;
            bx.w = (y + h*0.5f) + off;
        }
        g_boxes[b*KPRE + tid] = bx;
        unsigned bal = __ballot_sync(0xffffffffu, bits != 0u);
        if ((tid & 31) == 0) g_validw[b*32 + (tid >> 5)] = bal;
    }
    __syncthreads();
    if (tid == 0) g_cnt[b] = 0;   // reset for next replay
}

// ---------------- phase 3: IoU suppression bit-mask (upper triangle only) ----------------
__global__ void k_iou() {
    __shared__ float4 sb[1024];
    __shared__ float  sa[1024];
    __shared__ unsigned tileS[32][33];
    int b = blockIdx.y, tile = blockIdx.x;
    int tid = threadIdx.x;
    float4 v = g_boxes[b*KPRE + tid];
    sb[tid] = v;
    sa[tid] = (v.z - v.x) * (v.w - v.y);
    __syncthreads();

    int w = tid >> 5, rl = tid & 31;
    int r = tile*32 + rl;
    unsigned bits = 0u;
    if (w >= tile) {   // words below the diagonal are all-zero (j>i only)
        float4 rb_ = sb[r];
        float  ra  = sa[r];
        int j0 = w * 32;
        #pragma unroll 4
        for (int t = 0; t < 32; t++) {
            int j = j0 + t;
            float4 cb = sb[j];
            float ltx = fmaxf(rb_.x, cb.x), lty = fmaxf(rb_.y, cb.y);
            float rbx = fminf(rb_.z, cb.z), rby = fminf(rb_.w, cb.w);
            float iw = fmaxf(rbx - ltx, 0.f), ih = fmaxf(rby - lty, 0.f);
            float inter = iw * ih;
            float den = ((ra + sa[j]) - inter) + 1e-7f;
            float thr = 0.45f * den;
            bool sup;
            if (inter > thr * (1.0f + 1e-5f))       sup = true;
            else if (inter < thr * (1.0f - 1e-5f))  sup = false;
            else                                    sup = (__fdiv_rn(inter, den) > 0.45f);
            sup = sup && (j > r);
            bits |= sup ? (1u << t) : 0u;
        }
    }
    tileS[rl][w] = bits;
    __syncthreads();
    int rl2 = tid >> 5, w2 = tid & 31;
    g_mask[((size_t)b*KPRE + tile*32 + rl2) * 32 + w2] = tileS[rl2][w2];
}

// ---------------- phase 4: greedy reduction from SMEM with next-set-bit skipping ----------------
__global__ void k_nms() {
    extern __shared__ unsigned sm[];          // 1024 * 32 words = 128 KB
    int b = blockIdx.x, tid = threadIdx.x;    // 1024 threads
    const unsigned* mp = &g_mask[(size_t)b*KPRE*32];
    #pragma unroll
    for (int it = 0; it < 32; it++)
        sm[it*1024 + tid] = mp[it*1024 + tid];
    __syncthreads();

    if (tid < 32) {
        int lane = tid;
        unsigned alive = g_validw[b*32 + lane];   // lane holds indices [lane*32, lane*32+32)
        int cnt = 0;
        while (cnt < MAXDET) {
            unsigned bal = __ballot_sync(0xffffffffu, alive != 0u);
            if (!bal) break;
            int w = __ffs(bal) - 1;
            unsigned aw = __shfl_sync(0xffffffffu, alive, w);
            int i = w*32 + (__ffs(aw) - 1);
            unsigned row = sm[i*32 + lane];
            alive &= ~row;
            if (lane == w) alive &= ~(1u << (i & 31));
            if (lane == 0) g_sel[b*MAXDET + cnt] = i;
            cnt++;
        }
        if (lane == 0) g_nk[b] = cnt;
    }
}

// ---------------- phase 5: gather + emit output rows ----------------
__global__ void k_out(const float* __restrict__ pred,
                      const float* __restrict__ conf_logits,
                      const float* __restrict__ logits,
                      const float* __restrict__ head,
                      float* __restrict__ out) {
    int gw = (blockIdx.x * blockDim.x + threadIdx.x) >> 5;
    int lane = threadIdx.x & 31;
    if (gw >= BB*MAXDET) return;
    int b = gw / MAXDET, r = gw - b*MAXDET;
    size_t obase = (size_t)gw * OUTC;
    int nk = g_nk[b];
    if (r < nk) {
        int slot = g_sel[b*MAXDET + r];
        unsigned long long key = g_top[b*KPRE + slot];
        float score = __uint_as_float((unsigned)(key >> 32));
        unsigned anchor = (unsigned)key;
        size_t a = (size_t)b*NN + anchor;
        float objsig = 1.f / (1.f + expf(-conf_logits[a*5 + 4]));
        for (int c = lane; c < OUTC; c += 32) {
            float val;
            if (c < 4) {
                float x = pred[a*85], y = pred[a*85+1], w = pred[a*85+2], h = pred[a*85+3];
                val = (c == 0) ? x - w*0.5f : (c == 1) ? y - h*0.5f
                    : (c == 2) ? x + w*0.5f : y + h*0.5f;
            } else if (c == 4)  val = score;
            else if (c == 5)    val = (float)g_cls[a];
            else if (c < 86)    val = (1.f / (1.f + expf(-logits[a*80 + (c - 6)]))) * objsig;
            else if (c == 86)   val = objsig;
            else if (c == 87)   val = head[a];
            else                val = 1.f;
            out[obase + c] = val;
        }
    } else {
        for (int c = lane; c < OUTC; c += 32) out[obase + c] = 0.f;
    }
}

extern "C" void kernel_launch(void* const* d_in, const int* in_sizes, int n_in,
                              void* d_out, int out_size) {
    const float* pred = (const float*)d_in[0];
    const float* cl   = (const float*)d_in[1];
    const float* lg   = (const float*)d_in[2];
    const float* hd   = (const float*)d_in[3];
    float* out = (float*)d_out;

    cudaFuncSetAttribute(k_nms, cudaFuncAttributeMaxDynamicSharedMemorySize,
                         KPRE * 32 * (int)sizeof(unsigned));

    {
        // one warp per anchor, 8 anchors per 256-thread block; 25200 % 8 == 0
        int blocks = (BB*NN) / 8;
        k_score<<<blocks, 256>>>(pred);
    }
    k_sortsel<<<BB, 1024>>>(pred);
    k_iou<<<dim3(32, BB), 1024>>>();
    k_nms<<<BB, 1024, KPRE * 32 * sizeof(unsigned)>>>();
    k_out<<<(BB*MAXDET*32 + 255) / 256, 256>>>(pred, cl, lg, hd, out);
}